// round 2
// baseline (speedup 1.0000x reference)
#include <cuda_runtime.h>
#include <math.h>

#define NN     8192
#define NFEAT  512
#define NHID   128
#define NCLASS 16
#define SPLITK   4
#define SPLITK16 8

// ---------------- static device scratch (no allocs allowed) ----------------
__device__ float g_c0[NN];
__device__ float g_c1[NN];
__device__ float g_B[NN * NHID];                 // GEMM B operand (x@W1, h@Wm)
__device__ float g_h[NN * NHID];                 // hidden activations
__device__ float g_B16[NN * NCLASS];             // h2@W2
__device__ float g_part[SPLITK * NN * NHID];     // split-K partials (16 MB)
__device__ float g_part16[SPLITK16 * NN * NCLASS];

// ---------------- attention: c0/c1 per column ----------------
__global__ void attn_kernel(const float* __restrict__ adj0,
                            const float* __restrict__ adj1,
                            const float* __restrict__ aw,
                            const float* __restrict__ ab) {
    int row = blockIdx.x;
    const float4* a0 = reinterpret_cast<const float4*>(adj0 + (size_t)row * NN);
    const float4* a1 = reinterpret_cast<const float4*>(adj1 + (size_t)row * NN);
    const float4* w4 = reinterpret_cast<const float4*>(aw);
    float s0 = 0.f, s1 = 0.f;
    for (int i = threadIdx.x; i < NN / 4; i += blockDim.x) {
        float4 w  = w4[i];
        float4 v0 = a0[i];
        float4 v1 = a1[i];
        s0 += v0.x * w.x + v0.y * w.y + v0.z * w.z + v0.w * w.w;
        s1 += v1.x * w.x + v1.y * w.y + v1.z * w.z + v1.w * w.w;
    }
    #pragma unroll
    for (int o = 16; o > 0; o >>= 1) {
        s0 += __shfl_down_sync(0xffffffffu, s0, o);
        s1 += __shfl_down_sync(0xffffffffu, s1, o);
    }
    __shared__ float sh0[8], sh1[8];
    int warp = threadIdx.x >> 5, lane = threadIdx.x & 31;
    if (lane == 0) { sh0[warp] = s0; sh1[warp] = s1; }
    __syncthreads();
    if (threadIdx.x == 0) {
        float t0 = 0.f, t1 = 0.f;
        #pragma unroll
        for (int w = 0; w < 8; w++) { t0 += sh0[w]; t1 += sh1[w]; }
        float b  = ab[0];
        float z1 = t0 + b, z2 = t1 + b;
        float m  = fmaxf(z1, z2);
        float e1 = expf(z1 - m), e2 = expf(z2 - m);
        float inv = 1.f / (e1 + e2);
        g_c0[row] = e1 * inv;
        g_c1[row] = e2 * inv;
    }
}

// ---------------- split-K SGEMM, BN = 128 (full N), BM=64, BK=16 ----------
// ADJMIX: A tile = c0[k]*adj0 + c1[k]*adj1 combined at load time.
// Writes partials: part[split][M][128].
template <bool ADJMIX>
__global__ __launch_bounds__(128)
void gemm128_k(const float* __restrict__ A0, const float* __restrict__ A1,
               const float* __restrict__ Bm, float* __restrict__ part,
               int K, int kPerSplit) {
    __shared__ float As[16][64];
    __shared__ float Bs[16][128];

    const int r0   = blockIdx.x * 64;
    const int kBeg = blockIdx.y * kPerSplit;
    const int tid  = threadIdx.x;

    float acc[8][8];
    #pragma unroll
    for (int i = 0; i < 8; i++)
        #pragma unroll
        for (int j = 0; j < 8; j++) acc[i][j] = 0.f;

    const int tm = (tid >> 4) << 3;   // 0..56
    const int tn = (tid & 15) << 3;   // 0..120

    // A-tile loader mapping: thread loads 2 consecutive float4 of one row
    const int qa = tid << 1;
    const int am = qa >> 2;           // row in tile 0..63
    const int ak = (qa & 3) << 2;     // 0 or 8

    for (int kt = kBeg; kt < kBeg + kPerSplit; kt += 16) {
        // ---- load + (optionally) combine A tile [64 x 16] ----
        {
            const float* rp0 = A0 + (size_t)(r0 + am) * (size_t)K + kt + ak;
            float4 v0a = *reinterpret_cast<const float4*>(rp0);
            float4 v0b = *reinterpret_cast<const float4*>(rp0 + 4);
            if (ADJMIX) {
                const float* rp1 = A1 + (size_t)(r0 + am) * (size_t)K + kt + ak;
                float4 v1a = *reinterpret_cast<const float4*>(rp1);
                float4 v1b = *reinterpret_cast<const float4*>(rp1 + 4);
                float4 c0a = *reinterpret_cast<const float4*>(g_c0 + kt + ak);
                float4 c0b = *reinterpret_cast<const float4*>(g_c0 + kt + ak + 4);
                float4 c1a = *reinterpret_cast<const float4*>(g_c1 + kt + ak);
                float4 c1b = *reinterpret_cast<const float4*>(g_c1 + kt + ak + 4);
                v0a.x = c0a.x * v0a.x + c1a.x * v1a.x;
                v0a.y = c0a.y * v0a.y + c1a.y * v1a.y;
                v0a.z = c0a.z * v0a.z + c1a.z * v1a.z;
                v0a.w = c0a.w * v0a.w + c1a.w * v1a.w;
                v0b.x = c0b.x * v0b.x + c1b.x * v1b.x;
                v0b.y = c0b.y * v0b.y + c1b.y * v1b.y;
                v0b.z = c0b.z * v0b.z + c1b.z * v1b.z;
                v0b.w = c0b.w * v0b.w + c1b.w * v1b.w;
            }
            As[ak + 0][am] = v0a.x; As[ak + 1][am] = v0a.y;
            As[ak + 2][am] = v0a.z; As[ak + 3][am] = v0a.w;
            As[ak + 4][am] = v0b.x; As[ak + 5][am] = v0b.y;
            As[ak + 6][am] = v0b.z; As[ak + 7][am] = v0b.w;
        }
        // ---- load B tile [16 x 128] ----
        #pragma unroll
        for (int i = 0; i < 4; i++) {
            int q  = tid + (i << 7);
            int k  = q >> 5;
            int n4 = (q & 31) << 2;
            *reinterpret_cast<float4*>(&Bs[k][n4]) =
                *reinterpret_cast<const float4*>(Bm + (size_t)(kt + k) * NHID + n4);
        }
        __syncthreads();

        #pragma unroll
        for (int kk = 0; kk < 16; kk++) {
            float4 a0v = *reinterpret_cast<const float4*>(&As[kk][tm]);
            float4 a1v = *reinterpret_cast<const float4*>(&As[kk][tm + 4]);
            float4 b0v = *reinterpret_cast<const float4*>(&Bs[kk][tn]);
            float4 b1v = *reinterpret_cast<const float4*>(&Bs[kk][tn + 4]);
            float ra[8] = {a0v.x, a0v.y, a0v.z, a0v.w, a1v.x, a1v.y, a1v.z, a1v.w};
            float rb[8] = {b0v.x, b0v.y, b0v.z, b0v.w, b1v.x, b1v.y, b1v.z, b1v.w};
            #pragma unroll
            for (int i = 0; i < 8; i++)
                #pragma unroll
                for (int j = 0; j < 8; j++)
                    acc[i][j] = fmaf(ra[i], rb[j], acc[i][j]);
        }
        __syncthreads();
    }

    float* p = part + (size_t)blockIdx.y * ((size_t)NN * NHID);
    #pragma unroll
    for (int i = 0; i < 8; i++) {
        float* o = p + (size_t)(r0 + tm + i) * NHID + tn;
        #pragma unroll
        for (int j = 0; j < 8; j++) o[j] = acc[i][j];
    }
}

// ---------------- split-K GEMM for N = 16 (adj mix only) -------------------
__global__ __launch_bounds__(128)
void gemm16_k(const float* __restrict__ A0, const float* __restrict__ A1,
              const float* __restrict__ Bm, float* __restrict__ part,
              int kPerSplit) {
    __shared__ float As[32][64];
    __shared__ float Bs[32][16];

    const int r0   = blockIdx.x * 64;
    const int kBeg = blockIdx.y * kPerSplit;
    const int tid  = threadIdx.x;
    const int n    = tid & 15;
    const int mg   = (tid >> 4) << 3;

    float acc[8];
    #pragma unroll
    for (int i = 0; i < 8; i++) acc[i] = 0.f;

    for (int kt = kBeg; kt < kBeg + kPerSplit; kt += 32) {
        #pragma unroll
        for (int i = 0; i < 4; i++) {
            int q  = tid + (i << 7);
            int m  = q >> 3;
            int kc = (q & 7) << 2;
            const float* rp0 = A0 + (size_t)(r0 + m) * NN + kt + kc;
            const float* rp1 = A1 + (size_t)(r0 + m) * NN + kt + kc;
            float4 v0  = *reinterpret_cast<const float4*>(rp0);
            float4 v1  = *reinterpret_cast<const float4*>(rp1);
            float4 c0v = *reinterpret_cast<const float4*>(g_c0 + kt + kc);
            float4 c1v = *reinterpret_cast<const float4*>(g_c1 + kt + kc);
            As[kc + 0][m] = c0v.x * v0.x + c1v.x * v1.x;
            As[kc + 1][m] = c0v.y * v0.y + c1v.y * v1.y;
            As[kc + 2][m] = c0v.z * v0.z + c1v.z * v1.z;
            As[kc + 3][m] = c0v.w * v0.w + c1v.w * v1.w;
        }
        {
            int k  = tid >> 2;
            int n4 = (tid & 3) << 2;
            *reinterpret_cast<float4*>(&Bs[k][n4]) =
                *reinterpret_cast<const float4*>(Bm + (size_t)(kt + k) * NCLASS + n4);
        }
        __syncthreads();
        #pragma unroll
        for (int kk = 0; kk < 32; kk++) {
            float rb   = Bs[kk][n];
            float4 a0v = *reinterpret_cast<const float4*>(&As[kk][mg]);
            float4 a1v = *reinterpret_cast<const float4*>(&As[kk][mg + 4]);
            acc[0] = fmaf(a0v.x, rb, acc[0]);
            acc[1] = fmaf(a0v.y, rb, acc[1]);
            acc[2] = fmaf(a0v.z, rb, acc[2]);
            acc[3] = fmaf(a0v.w, rb, acc[3]);
            acc[4] = fmaf(a1v.x, rb, acc[4]);
            acc[5] = fmaf(a1v.y, rb, acc[5]);
            acc[6] = fmaf(a1v.z, rb, acc[6]);
            acc[7] = fmaf(a1v.w, rb, acc[7]);
        }
        __syncthreads();
    }
    float* p = part + (size_t)blockIdx.y * ((size_t)NN * NCLASS);
    #pragma unroll
    for (int i = 0; i < 8; i++)
        p[(size_t)(r0 + mg + i) * NCLASS + n] = acc[i];
}

// ---------------- split-K reduce + bias + relu (width 128) -----------------
__global__ void reduce_ep(const float* __restrict__ part,
                          const float* __restrict__ bias,
                          float* __restrict__ outp, int doRelu) {
    int idx = blockIdx.x * blockDim.x + threadIdx.x;  // < NN*NHID
    const int stride = NN * NHID;
    float s = part[idx] + part[idx + stride] + part[idx + 2 * stride] + part[idx + 3 * stride];
    if (bias) s += bias[idx & (NHID - 1)];
    if (doRelu) s = fmaxf(s, 0.f);
    outp[idx] = s;
}

// ---------------- h2 @ W2  ([8192,128]@[128,16]) ---------------------------
__global__ void hw2_kernel(const float* __restrict__ h, const float* __restrict__ W2,
                           float* __restrict__ outp) {
    __shared__ float sW[NHID * NCLASS];
    __shared__ float sH[16][NHID];
    int tid = threadIdx.x;
    for (int i = tid; i < NHID * NCLASS; i += 256) sW[i] = W2[i];
    int r0 = blockIdx.x * 16;
    for (int i = tid; i < 16 * NHID; i += 256)
        sH[i >> 7][i & 127] = h[(size_t)r0 * NHID + i];
    __syncthreads();
    int r = tid >> 4, n = tid & 15;
    float acc = 0.f;
    #pragma unroll 8
    for (int k = 0; k < NHID; k++) acc = fmaf(sH[r][k], sW[k * NCLASS + n], acc);
    outp[(size_t)(r0 + r) * NCLASS + n] = acc;
}

// ---------------- final: reduce split-K 16-wide + bias + row softmax -------
__global__ void final16_kernel(const float* __restrict__ part, const float* __restrict__ b2,
                               float* __restrict__ outp) {
    int gid = blockIdx.x * 256 + threadIdx.x;  // < NN*NCLASS
    int n   = gid & 15;
    float z = b2[n];
    const int stride = NN * NCLASS;
    #pragma unroll
    for (int s = 0; s < SPLITK16; s++) z += part[s * stride + gid];
    float m = z;
    #pragma unroll
    for (int o = 8; o > 0; o >>= 1) m = fmaxf(m, __shfl_xor_sync(0xffffffffu, m, o));
    float e = expf(z - m);
    float ss = e;
    #pragma unroll
    for (int o = 8; o > 0; o >>= 1) ss += __shfl_xor_sync(0xffffffffu, ss, o);
    outp[gid] = e / ss;
}

// ---------------- launch ---------------------------------------------------
extern "C" void kernel_launch(void* const* d_in, const int* in_sizes, int n_in,
                              void* d_out, int out_size) {
    const float* adj0 = (const float*)d_in[0];
    const float* adj1 = (const float*)d_in[1];
    const float* x    = (const float*)d_in[2];
    const float* aw   = (const float*)d_in[3];
    const float* ab   = (const float*)d_in[4];
    const float* W1   = (const float*)d_in[5];
    const float* b1   = (const float*)d_in[6];
    const float* Wm   = (const float*)d_in[7];
    const float* bm   = (const float*)d_in[8];
    const float* W2   = (const float*)d_in[9];
    const float* b2   = (const float*)d_in[10];
    float* out = (float*)d_out;

    float *pB, *ph, *pB16, *ppart, *ppart16;
    cudaGetSymbolAddress((void**)&pB,      g_B);
    cudaGetSymbolAddress((void**)&ph,      g_h);
    cudaGetSymbolAddress((void**)&pB16,    g_B16);
    cudaGetSymbolAddress((void**)&ppart,   g_part);
    cudaGetSymbolAddress((void**)&ppart16, g_part16);

    // attention weights per column
    attn_kernel<<<NN, 256>>>(adj0, adj1, aw, ab);

    // H0 = x @ W1
    gemm128_k<false><<<dim3(NN / 64, SPLITK), 128>>>(x, nullptr, W1, ppart, NFEAT, NFEAT / SPLITK);
    reduce_ep<<<NN * NHID / 256, 256>>>(ppart, nullptr, pB, 0);

    // h1 = relu(adj @ H0 + b1)
    gemm128_k<true><<<dim3(NN / 64, SPLITK), 128>>>(adj0, adj1, pB, ppart, NN, NN / SPLITK);
    reduce_ep<<<NN * NHID / 256, 256>>>(ppart, b1, ph, 1);

    // H1 = h1 @ Wm
    gemm128_k<false><<<dim3(NN / 64, SPLITK), 128>>>(ph, nullptr, Wm, ppart, NHID, NHID / SPLITK);
    reduce_ep<<<NN * NHID / 256, 256>>>(ppart, nullptr, pB, 0);

    // h2 = relu(adj @ H1 + bm)
    gemm128_k<true><<<dim3(NN / 64, SPLITK), 128>>>(adj0, adj1, pB, ppart, NN, NN / SPLITK);
    reduce_ep<<<NN * NHID / 256, 256>>>(ppart, bm, ph, 1);

    // H2 = h2 @ W2
    hw2_kernel<<<NN / 16, 256>>>(ph, W2, pB16);

    // z = adj @ H2 + b2 ; softmax rows
    gemm16_k<<<dim3(NN / 64, SPLITK16), 128>>>(adj0, adj1, pB16, ppart16, NN / SPLITK16);
    final16_kernel<<<NN * NCLASS / 256, 256>>>(ppart16, b2, out);
}

// round 5
// speedup vs baseline: 1.4337x; 1.4337x over previous
#include <cuda_runtime.h>
#include <cuda_bf16.h>
#include <math.h>
#include <stdint.h>

#define NN     8192
#define NFEAT  512
#define NHID   128
#define NCLASS 16
#define SPLITK 4

// ---------------- static device scratch ----------------
__device__ float g_c0[NN];
__device__ float g_c1[NN];
__device__ float g_B[NN * NHID];
__device__ float g_h[NN * NHID];
__device__ float g_B16[NN * NCLASS];
__device__ float g_part[SPLITK * NN * NHID];
__device__ float g_part16[SPLITK * NN * NCLASS];
// 4 term-buffers: [c0*H hi][c0*H lo][c1*H hi][c1*H lo], each [BN][NN] row-major (n-major, k contiguous)
__device__ __nv_bfloat16 g_bt[4 * NN * NHID];

// ---------------- helpers ----------------
__device__ __forceinline__ uint32_t smem_to_u32(const void* p) {
    uint32_t a;
    asm("{ .reg .u64 t; cvta.to.shared.u64 t, %1; cvt.u32.u64 %0, t; }" : "=r"(a) : "l"(p));
    return a;
}
#define CP_ASYNC16(sm, g) \
    asm volatile("cp.async.cg.shared.global [%0], [%1], 16;" :: "r"((uint32_t)(sm)), "l"(g) : "memory")
#define CP_COMMIT() asm volatile("cp.async.commit_group;" ::: "memory")
#define CP_WAIT0()  asm volatile("cp.async.wait_group 0;" ::: "memory")

__device__ __forceinline__ void ldsm4(uint32_t addr, uint32_t& r0, uint32_t& r1,
                                      uint32_t& r2, uint32_t& r3) {
    asm volatile("ldmatrix.sync.aligned.m8n8.x4.shared.b16 {%0,%1,%2,%3}, [%4];"
                 : "=r"(r0), "=r"(r1), "=r"(r2), "=r"(r3) : "r"(addr));
}
__device__ __forceinline__ void mma16816(float* d, const uint32_t* a, const uint32_t* b) {
    asm volatile("mma.sync.aligned.m16n8k16.row.col.f32.bf16.bf16.f32 "
                 "{%0,%1,%2,%3}, {%4,%5,%6,%7}, {%8,%9}, {%0,%1,%2,%3};"
                 : "+f"(d[0]), "+f"(d[1]), "+f"(d[2]), "+f"(d[3])
                 : "r"(a[0]), "r"(a[1]), "r"(a[2]), "r"(a[3]), "r"(b[0]), "r"(b[1]));
}
// hi/lo bf16 split of two floats, packed as bf16x2 words (low half = first elem)
__device__ __forceinline__ void split2(float a, float b, unsigned& hi, unsigned& lo) {
    __nv_bfloat162 h = __float22bfloat162_rn(make_float2(a, b));
    float2 hf = __bfloat1622float2(h);
    __nv_bfloat162 l = __float22bfloat162_rn(make_float2(a - hf.x, b - hf.y));
    hi = *reinterpret_cast<unsigned*>(&h);
    lo = *reinterpret_cast<unsigned*>(&l);
}

// ---------------- attention: c0/c1 per column ----------------
__global__ void attn_kernel(const float* __restrict__ adj0, const float* __restrict__ adj1,
                            const float* __restrict__ aw, const float* __restrict__ ab) {
    int row = blockIdx.x;
    const float4* a0 = reinterpret_cast<const float4*>(adj0 + (size_t)row * NN);
    const float4* a1 = reinterpret_cast<const float4*>(adj1 + (size_t)row * NN);
    const float4* w4 = reinterpret_cast<const float4*>(aw);
    float s0 = 0.f, s1 = 0.f;
    for (int i = threadIdx.x; i < NN / 4; i += blockDim.x) {
        float4 w = w4[i], v0 = a0[i], v1 = a1[i];
        s0 += v0.x * w.x + v0.y * w.y + v0.z * w.z + v0.w * w.w;
        s1 += v1.x * w.x + v1.y * w.y + v1.z * w.z + v1.w * w.w;
    }
    #pragma unroll
    for (int o = 16; o > 0; o >>= 1) {
        s0 += __shfl_down_sync(0xffffffffu, s0, o);
        s1 += __shfl_down_sync(0xffffffffu, s1, o);
    }
    __shared__ float sh0[8], sh1[8];
    int warp = threadIdx.x >> 5, lane = threadIdx.x & 31;
    if (lane == 0) { sh0[warp] = s0; sh1[warp] = s1; }
    __syncthreads();
    if (threadIdx.x == 0) {
        float t0 = 0.f, t1 = 0.f;
        #pragma unroll
        for (int w = 0; w < 8; w++) { t0 += sh0[w]; t1 += sh1[w]; }
        float b = ab[0];
        float z1 = t0 + b, z2 = t1 + b;
        float m = fmaxf(z1, z2);
        float e1 = expf(z1 - m), e2 = expf(z2 - m);
        float inv = 1.f / (e1 + e2);
        g_c0[row] = e1 * inv;
        g_c1[row] = e2 * inv;
    }
}

// ---------------- B precompute: bt[t][n][k] = split_t(c[k] * H[k][n]) -------
template <int BN>
__global__ void prep_bt(const float* __restrict__ H, __nv_bfloat16* __restrict__ bt) {
    __shared__ float sH[64][BN + 1];
    __shared__ float sc0[64], sc1[64];
    const int k0 = blockIdx.x * 64;
    const int tid = threadIdx.x;
    for (int idx = tid; idx < 64 * BN; idx += 256) {
        int r = idx / BN, n = idx % BN;
        sH[r][n] = H[(size_t)(k0 + r) * BN + n];
    }
    if (tid < 64) sc0[tid] = g_c0[k0 + tid];
    else if (tid < 128) sc1[tid - 64] = g_c1[k0 + tid - 64];
    __syncthreads();
    const int w = tid >> 5, p = tid & 31;
    const size_t MATB = (size_t)NN * BN;  // elements per term buffer
    for (int n = w; n < BN; n += 8) {
        float h0 = sH[2 * p][n], h1 = sH[2 * p + 1][n];
        unsigned* base = reinterpret_cast<unsigned*>(bt + (size_t)n * NN + k0 + 2 * p);
        unsigned hi, lo;
        split2(sc0[2 * p] * h0, sc0[2 * p + 1] * h1, hi, lo);
        base[0] = hi;
        *reinterpret_cast<unsigned*>(bt + 1 * MATB + (size_t)n * NN + k0 + 2 * p) = lo;
        split2(sc1[2 * p] * h0, sc1[2 * p + 1] * h1, hi, lo);
        *reinterpret_cast<unsigned*>(bt + 2 * MATB + (size_t)n * NN + k0 + 2 * p) = hi;
        *reinterpret_cast<unsigned*>(bt + 3 * MATB + (size_t)n * NN + k0 + 2 * p) = lo;
    }
}

// ---------------- mma.sync layer GEMM: D = adj0@B0 + adj1@B1 (3-term bf16) --
// BM=128, BK=32, grid (64, SPLITK), 256 threads. A fp32 streamed+split in-kernel.
template <int BN>
__global__ __launch_bounds__(256, 1)
void gemm_ws(const float* __restrict__ A0g, const float* __restrict__ A1g,
             const __nv_bfloat16* __restrict__ btg, float* __restrict__ part) {
    extern __shared__ char smem[];
    constexpr int ATILE = 128 * 80;          // one bf16 A tile (padded rows)
    constexpr int A4 = 4 * ATILE;            // a0hi a0lo a1hi a1lo
    constexpr int BTILE = BN * 80;
    constexpr int B4 = 4 * BTILE;
    constexpr int KCH = NN / SPLITK;         // 2048
    constexpr int NITER = KCH / 32;          // 64
    constexpr size_t MATB2 = (size_t)NN * BN * 2;  // bytes per term buffer
    constexpr int MT = (BN == 128) ? 2 : 1;
    constexpr int NT = (BN == 128) ? 8 : 2;

    const int tid = threadIdx.x, wid = tid >> 5, lane = tid & 31;
    const int r0 = blockIdx.x * 128;
    const int kBeg = blockIdx.y * KCH;
    const uint32_t sb = smem_to_u32(smem);
    const int wm = (BN == 128) ? (wid & 3) : wid;
    const int wn = (BN == 128) ? (wid >> 2) : 0;
    const int mBase = wm * (MT * 16);
    const int nBase = wn * (NT * 8);

    float acc[MT][NT][4];
    #pragma unroll
    for (int i = 0; i < MT; i++)
        #pragma unroll
        for (int j = 0; j < NT; j++)
            #pragma unroll
            for (int q = 0; q < 4; q++) acc[i][j][q] = 0.f;

    float4 ra[8];

    auto ldgA = [&](int it) {
        #pragma unroll
        for (int j = 0; j < 8; j++) {
            int id = tid + j * 256;
            int mat = id >> 10, row = (id >> 3) & 127, c4 = id & 7;
            const float* g = (mat ? A1g : A0g) + (size_t)(r0 + row) * NN + kBeg + it * 32 + c4 * 4;
            ra[j] = *reinterpret_cast<const float4*>(g);
        }
    };
    auto stA = [&](int d) {
        #pragma unroll
        for (int j = 0; j < 8; j++) {
            int id = tid + j * 256;
            int mat = id >> 10, row = (id >> 3) & 127, c4 = id & 7;
            unsigned h0, l0, h1, l1;
            split2(ra[j].x, ra[j].y, h0, l0);
            split2(ra[j].z, ra[j].w, h1, l1);
            char* base = smem + d * A4 + mat * 2 * ATILE + row * 80 + c4 * 8;
            *reinterpret_cast<uint2*>(base) = make_uint2(h0, h1);
            *reinterpret_cast<uint2*>(base + ATILE) = make_uint2(l0, l1);
        }
    };
    auto cpB = [&](int it, int d) {
        const char* gb = reinterpret_cast<const char*>(btg);
        const int kb = (kBeg + it * 32) * 2;
        if (BN == 128) {
            #pragma unroll
            for (int j = 0; j < 8; j++) {
                int op = tid + j * 256;
                int buf = op >> 9, n = (op >> 2) & 127, ch = op & 3;
                uint32_t dst = sb + 2 * A4 + d * B4 + buf * BTILE + n * 80 + ch * 16;
                const char* src = gb + (size_t)buf * MATB2 + (size_t)n * (NN * 2) + kb + ch * 16;
                CP_ASYNC16(dst, src);
            }
        } else {
            int op = tid;
            if (op < 256) {
                int buf = op >> 6, n = (op >> 2) & 15, ch = op & 3;
                uint32_t dst = sb + 2 * A4 + d * B4 + buf * BTILE + n * 80 + ch * 16;
                const char* src = gb + (size_t)buf * MATB2 + (size_t)n * (NN * 2) + kb + ch * 16;
                CP_ASYNC16(dst, src);
            }
        }
        CP_COMMIT();
    };
    auto domma = [&](int d) {
        const int ta[6] = {0, 0, 1, 2, 2, 3};
        const int tb[6] = {0, 1, 0, 2, 3, 2};
        #pragma unroll
        for (int t = 0; t < 6; t++) {
            #pragma unroll
            for (int kk = 0; kk < 2; kk++) {
                uint32_t af[MT][4];
                #pragma unroll
                for (int mi = 0; mi < MT; mi++) {
                    uint32_t addr = sb + d * A4 + ta[t] * ATILE
                                  + (mBase + mi * 16 + (lane & 15)) * 80
                                  + ((lane >> 4) << 4) + kk * 32;
                    ldsm4(addr, af[mi][0], af[mi][1], af[mi][2], af[mi][3]);
                }
                uint32_t bf[NT][2];
                #pragma unroll
                for (int np = 0; np < NT / 2; np++) {
                    uint32_t addr = sb + 2 * A4 + d * B4 + tb[t] * BTILE
                                  + (nBase + np * 16 + ((lane >> 4) << 3) + (lane & 7)) * 80
                                  + (((lane >> 3) & 1) << 4) + kk * 32;
                    ldsm4(addr, bf[2 * np][0], bf[2 * np][1], bf[2 * np + 1][0], bf[2 * np + 1][1]);
                }
                #pragma unroll
                for (int mi = 0; mi < MT; mi++)
                    #pragma unroll
                    for (int ni = 0; ni < NT; ni++)
                        mma16816(acc[mi][ni], af[mi], bf[ni]);
            }
        }
    };

    // prologue
    ldgA(0);
    stA(0);
    cpB(0, 0);
    if (NITER > 1) ldgA(1);

    for (int it = 0; it < NITER; ++it) {
        const int c = it & 1;
        CP_WAIT0();
        __syncthreads();
        if (it + 1 < NITER) stA(1 - c);
        if (it + 2 < NITER) ldgA(it + 2);
        if (it + 1 < NITER) cpB(it + 1, 1 - c);
        else CP_COMMIT();
        domma(c);
    }

    float* op0 = part + (size_t)blockIdx.y * ((size_t)NN * BN);
    #pragma unroll
    for (int mi = 0; mi < MT; mi++)
        #pragma unroll
        for (int ni = 0; ni < NT; ni++) {
            int row = r0 + mBase + mi * 16 + (lane >> 2);
            int col = nBase + ni * 8 + (lane & 3) * 2;
            *reinterpret_cast<float2*>(op0 + (size_t)row * BN + col) =
                make_float2(acc[mi][ni][0], acc[mi][ni][1]);
            *reinterpret_cast<float2*>(op0 + (size_t)(row + 8) * BN + col) =
                make_float2(acc[mi][ni][2], acc[mi][ni][3]);
        }
}

// ---------------- FFMA SGEMM for the small dense GEMMs (x@W1, h@Wm) --------
__global__ __launch_bounds__(128)
void gemm128_k(const float* __restrict__ A0, const float* __restrict__ Bm,
               float* __restrict__ part, int K, int kPerSplit) {
    __shared__ float As[16][64];
    __shared__ float Bs[16][128];
    const int r0 = blockIdx.x * 64;
    const int kBeg = blockIdx.y * kPerSplit;
    const int tid = threadIdx.x;
    float acc[8][8];
    #pragma unroll
    for (int i = 0; i < 8; i++)
        #pragma unroll
        for (int j = 0; j < 8; j++) acc[i][j] = 0.f;
    const int tm = (tid >> 4) << 3;
    const int tn = (tid & 15) << 3;
    const int qa = tid << 1;
    const int am = qa >> 2;
    const int ak = (qa & 3) << 2;
    for (int kt = kBeg; kt < kBeg + kPerSplit; kt += 16) {
        {
            const float* rp0 = A0 + (size_t)(r0 + am) * (size_t)K + kt + ak;
            float4 v0a = *reinterpret_cast<const float4*>(rp0);
            float4 v0b = *reinterpret_cast<const float4*>(rp0 + 4);
            As[ak + 0][am] = v0a.x; As[ak + 1][am] = v0a.y;
            As[ak + 2][am] = v0a.z; As[ak + 3][am] = v0a.w;
            As[ak + 4][am] = v0b.x; As[ak + 5][am] = v0b.y;
            As[ak + 6][am] = v0b.z; As[ak + 7][am] = v0b.w;
        }
        #pragma unroll
        for (int i = 0; i < 4; i++) {
            int q = tid + (i << 7);
            int k = q >> 5;
            int n4 = (q & 31) << 2;
            *reinterpret_cast<float4*>(&Bs[k][n4]) =
                *reinterpret_cast<const float4*>(Bm + (size_t)(kt + k) * NHID + n4);
        }
        __syncthreads();
        #pragma unroll
        for (int kk = 0; kk < 16; kk++) {
            float4 a0v = *reinterpret_cast<const float4*>(&As[kk][tm]);
            float4 a1v = *reinterpret_cast<const float4*>(&As[kk][tm + 4]);
            float4 b0v = *reinterpret_cast<const float4*>(&Bs[kk][tn]);
            float4 b1v = *reinterpret_cast<const float4*>(&Bs[kk][tn + 4]);
            float rav[8] = {a0v.x, a0v.y, a0v.z, a0v.w, a1v.x, a1v.y, a1v.z, a1v.w};
            float rbv[8] = {b0v.x, b0v.y, b0v.z, b0v.w, b1v.x, b1v.y, b1v.z, b1v.w};
            #pragma unroll
            for (int i = 0; i < 8; i++)
                #pragma unroll
                for (int j = 0; j < 8; j++)
                    acc[i][j] = fmaf(rav[i], rbv[j], acc[i][j]);
        }
        __syncthreads();
    }
    float* p = part + (size_t)blockIdx.y * ((size_t)NN * NHID);
    #pragma unroll
    for (int i = 0; i < 8; i++) {
        float* o = p + (size_t)(r0 + tm + i) * NHID + tn;
        #pragma unroll
        for (int j = 0; j < 8; j++) o[j] = acc[i][j];
    }
}

// ---------------- split-K reduce + bias + relu (width 128) -----------------
__global__ void reduce_ep(const float* __restrict__ part, const float* __restrict__ bias,
                          float* __restrict__ outp, int doRelu) {
    int idx = blockIdx.x * blockDim.x + threadIdx.x;
    const int stride = NN * NHID;
    float s = part[idx] + part[idx + stride] + part[idx + 2 * stride] + part[idx + 3 * stride];
    if (bias) s += bias[idx & (NHID - 1)];
    if (doRelu) s = fmaxf(s, 0.f);
    outp[idx] = s;
}

// ---------------- h2 @ W2 ----------------
__global__ void hw2_kernel(const float* __restrict__ h, const float* __restrict__ W2,
                           float* __restrict__ outp) {
    __shared__ float sW[NHID * NCLASS];
    __shared__ float sH[16][NHID];
    int tid = threadIdx.x;
    for (int i = tid; i < NHID * NCLASS; i += 256) sW[i] = W2[i];
    int r0 = blockIdx.x * 16;
    for (int i = tid; i < 16 * NHID; i += 256) sH[i >> 7][i & 127] = h[(size_t)r0 * NHID + i];
    __syncthreads();
    int r = tid >> 4, n = tid & 15;
    float acc = 0.f;
    #pragma unroll 8
    for (int k = 0; k < NHID; k++) acc = fmaf(sH[r][k], sW[k * NCLASS + n], acc);
    outp[(size_t)(r0 + r) * NCLASS + n] = acc;
}

// ---------------- final: reduce splits + bias + row softmax ----------------
__global__ void final16_kernel(const float* __restrict__ part, const float* __restrict__ b2,
                               float* __restrict__ outp) {
    int gid = blockIdx.x * 256 + threadIdx.x;
    int n = gid & 15;
    float z = b2[n];
    const int stride = NN * NCLASS;
    #pragma unroll
    for (int s = 0; s < SPLITK; s++) z += part[s * stride + gid];
    float m = z;
    #pragma unroll
    for (int o = 8; o > 0; o >>= 1) m = fmaxf(m, __shfl_xor_sync(0xffffffffu, m, o));
    float e = expf(z - m);
    float ss = e;
    #pragma unroll
    for (int o = 8; o > 0; o >>= 1) ss += __shfl_xor_sync(0xffffffffu, ss, o);
    outp[gid] = e / ss;
}

// ---------------- launch ---------------------------------------------------
extern "C" void kernel_launch(void* const* d_in, const int* in_sizes, int n_in,
                              void* d_out, int out_size) {
    const float* adj0 = (const float*)d_in[0];
    const float* adj1 = (const float*)d_in[1];
    const float* x    = (const float*)d_in[2];
    const float* aw   = (const float*)d_in[3];
    const float* ab   = (const float*)d_in[4];
    const float* W1   = (const float*)d_in[5];
    const float* b1   = (const float*)d_in[6];
    const float* Wm   = (const float*)d_in[7];
    const float* bm   = (const float*)d_in[8];
    const float* W2   = (const float*)d_in[9];
    const float* b2   = (const float*)d_in[10];
    float* out = (float*)d_out;

    float *pB, *ph, *pB16, *ppart, *ppart16;
    __nv_bfloat16* pbt;
    cudaGetSymbolAddress((void**)&pB, g_B);
    cudaGetSymbolAddress((void**)&ph, g_h);
    cudaGetSymbolAddress((void**)&pB16, g_B16);
    cudaGetSymbolAddress((void**)&ppart, g_part);
    cudaGetSymbolAddress((void**)&ppart16, g_part16);
    cudaGetSymbolAddress((void**)&pbt, g_bt);

    const int SMEM128 = 2 * (4 * 128 * 80) + 2 * (4 * 128 * 80);  // 163840
    const int SMEM16  = 2 * (4 * 128 * 80) + 2 * (4 * 16 * 80);   //  92160
    cudaFuncSetAttribute(gemm_ws<128>, cudaFuncAttributeMaxDynamicSharedMemorySize, SMEM128);
    cudaFuncSetAttribute(gemm_ws<16>,  cudaFuncAttributeMaxDynamicSharedMemorySize, SMEM16);

    // attention column weights
    attn_kernel<<<NN, 256>>>(adj0, adj1, aw, ab);

    // H0 = x @ W1
    gemm128_k<<<dim3(NN / 64, SPLITK), 128>>>(x, W1, ppart, NFEAT, NFEAT / SPLITK);
    reduce_ep<<<NN * NHID / 256, 256>>>(ppart, nullptr, pB, 0);

    // h1 = relu(adj0@(c0*H0) + adj1@(c1*H0) + b1)
    prep_bt<128><<<128, 256>>>(pB, pbt);
    gemm_ws<128><<<dim3(NN / 128, SPLITK), 256, SMEM128>>>(adj0, adj1, pbt, ppart);
    reduce_ep<<<NN * NHID / 256, 256>>>(ppart, b1, ph, 1);

    // H1 = h1 @ Wm
    gemm128_k<<<dim3(NN / 64, SPLITK), 128>>>(ph, Wm, ppart, NHID, NHID / SPLITK);
    reduce_ep<<<NN * NHID / 256, 256>>>(ppart, nullptr, pB, 0);

    // h2 = relu(adj0@(c0*H1) + adj1@(c1*H1) + bm)
    prep_bt<128><<<128, 256>>>(pB, pbt);
    gemm_ws<128><<<dim3(NN / 128, SPLITK), 256, SMEM128>>>(adj0, adj1, pbt, ppart);
    reduce_ep<<<NN * NHID / 256, 256>>>(ppart, bm, ph, 1);

    // H2 = h2 @ W2
    hw2_kernel<<<NN / 16, 256>>>(ph, W2, pB16);

    // z = adj0@(c0*H2) + adj1@(c1*H2) + b2 ; softmax rows
    prep_bt<16><<<128, 256>>>(pB16, pbt);
    gemm_ws<16><<<dim3(NN / 128, SPLITK), 256, SMEM16>>>(adj0, adj1, pbt, ppart16);
    final16_kernel<<<NN * NCLASS / 256, 256>>>(ppart16, b2, out);
}

// round 7
// speedup vs baseline: 1.8810x; 1.3120x over previous
#include <cuda_runtime.h>
#include <cuda_bf16.h>
#include <math.h>
#include <stdint.h>

#define NN     8192
#define NFEAT  512
#define NHID   128
#define NCLASS 16
#define SPLITK 4

// ---------------- static device scratch ----------------
__device__ float g_c0[NN];
__device__ float g_c1[NN];
__device__ float g_B[NN * NHID];
__device__ float g_h[NN * NHID];
__device__ float g_B16[NN * NCLASS];
__device__ float g_part[SPLITK * NN * NHID];
__device__ float g_part16[SPLITK * NN * NCLASS];
__device__ __nv_bfloat16 g_bt[2 * NN * NHID];   // H split: [hi][lo], each [BN][NN] (n-major)
__device__ __nv_bfloat16 g_ahi[(size_t)NN * NN];  // premixed adj hi (128 MB)
__device__ __nv_bfloat16 g_alo[(size_t)NN * NN];  // premixed adj lo (128 MB)

// ---------------- helpers ----------------
__device__ __forceinline__ uint32_t smem_to_u32(const void* p) {
    uint32_t a;
    asm("{ .reg .u64 t; cvta.to.shared.u64 t, %1; cvt.u32.u64 %0, t; }" : "=r"(a) : "l"(p));
    return a;
}
#define CP_ASYNC16(sm, g) \
    asm volatile("cp.async.cg.shared.global [%0], [%1], 16;" :: "r"((uint32_t)(sm)), "l"(g) : "memory")
#define CP_COMMIT() asm volatile("cp.async.commit_group;" ::: "memory")
#define CP_WAIT0()  asm volatile("cp.async.wait_group 0;" ::: "memory")
#define CP_WAIT1()  asm volatile("cp.async.wait_group 1;" ::: "memory")

__device__ __forceinline__ void ldsm4(uint32_t addr, uint32_t& r0, uint32_t& r1,
                                      uint32_t& r2, uint32_t& r3) {
    asm volatile("ldmatrix.sync.aligned.m8n8.x4.shared.b16 {%0,%1,%2,%3}, [%4];"
                 : "=r"(r0), "=r"(r1), "=r"(r2), "=r"(r3) : "r"(addr));
}
__device__ __forceinline__ void mma16816(float* d, const uint32_t* a, const uint32_t* b) {
    asm volatile("mma.sync.aligned.m16n8k16.row.col.f32.bf16.bf16.f32 "
                 "{%0,%1,%2,%3}, {%4,%5,%6,%7}, {%8,%9}, {%0,%1,%2,%3};"
                 : "+f"(d[0]), "+f"(d[1]), "+f"(d[2]), "+f"(d[3])
                 : "r"(a[0]), "r"(a[1]), "r"(a[2]), "r"(a[3]), "r"(b[0]), "r"(b[1]));
}
// hi/lo bf16 split of two floats, packed as bf16x2 words (low half = first elem)
__device__ __forceinline__ void split2(float a, float b, unsigned& hi, unsigned& lo) {
    __nv_bfloat162 h = __float22bfloat162_rn(make_float2(a, b));
    float2 hf = __bfloat1622float2(h);
    __nv_bfloat162 l = __float22bfloat162_rn(make_float2(a - hf.x, b - hf.y));
    hi = *reinterpret_cast<unsigned*>(&h);
    lo = *reinterpret_cast<unsigned*>(&l);
}

// ---------------- attention: c0/c1 per column ----------------
__global__ void attn_kernel(const float* __restrict__ adj0, const float* __restrict__ adj1,
                            const float* __restrict__ aw, const float* __restrict__ ab) {
    int row = blockIdx.x;
    const float4* a0 = reinterpret_cast<const float4*>(adj0 + (size_t)row * NN);
    const float4* a1 = reinterpret_cast<const float4*>(adj1 + (size_t)row * NN);
    const float4* w4 = reinterpret_cast<const float4*>(aw);
    float s0 = 0.f, s1 = 0.f;
    for (int i = threadIdx.x; i < NN / 4; i += blockDim.x) {
        float4 w = w4[i], v0 = a0[i], v1 = a1[i];
        s0 += v0.x * w.x + v0.y * w.y + v0.z * w.z + v0.w * w.w;
        s1 += v1.x * w.x + v1.y * w.y + v1.z * w.z + v1.w * w.w;
    }
    #pragma unroll
    for (int o = 16; o > 0; o >>= 1) {
        s0 += __shfl_down_sync(0xffffffffu, s0, o);
        s1 += __shfl_down_sync(0xffffffffu, s1, o);
    }
    __shared__ float sh0[8], sh1[8];
    int warp = threadIdx.x >> 5, lane = threadIdx.x & 31;
    if (lane == 0) { sh0[warp] = s0; sh1[warp] = s1; }
    __syncthreads();
    if (threadIdx.x == 0) {
        float t0 = 0.f, t1 = 0.f;
        #pragma unroll
        for (int w = 0; w < 8; w++) { t0 += sh0[w]; t1 += sh1[w]; }
        float b = ab[0];
        float z1 = t0 + b, z2 = t1 + b;
        float m = fmaxf(z1, z2);
        float e1 = expf(z1 - m), e2 = expf(z2 - m);
        float inv = 1.f / (e1 + e2);
        g_c0[row] = e1 * inv;
        g_c1[row] = e2 * inv;
    }
}

// ---------------- premix: adjmix = c0[k]*adj0 + c1[k]*adj1, bf16 hi/lo ------
__global__ __launch_bounds__(256)
void premix_kernel(const float* __restrict__ adj0, const float* __restrict__ adj1,
                   __nv_bfloat16* __restrict__ ahi, __nv_bfloat16* __restrict__ alo) {
    const size_t rb = (size_t)blockIdx.x * NN;
    const float4* a0 = reinterpret_cast<const float4*>(adj0 + rb);
    const float4* a1 = reinterpret_cast<const float4*>(adj1 + rb);
    for (int i = threadIdx.x; i < NN / 4; i += blockDim.x) {
        float4 v0 = a0[i], v1 = a1[i];
        float4 c0 = *reinterpret_cast<const float4*>(g_c0 + 4 * i);
        float4 c1 = *reinterpret_cast<const float4*>(g_c1 + 4 * i);
        float mx = c0.x * v0.x + c1.x * v1.x;
        float my = c0.y * v0.y + c1.y * v1.y;
        float mz = c0.z * v0.z + c1.z * v1.z;
        float mw = c0.w * v0.w + c1.w * v1.w;
        unsigned h0, l0, h1, l1;
        split2(mx, my, h0, l0);
        split2(mz, mw, h1, l1);
        *reinterpret_cast<uint2*>(ahi + rb + 4 * i) = make_uint2(h0, h1);
        *reinterpret_cast<uint2*>(alo + rb + 4 * i) = make_uint2(l0, l1);
    }
}

// ---------------- B precompute: bt[hi/lo][n][k] = split(H[k][n]) ------------
template <int BN>
__global__ void prep_bt(const float* __restrict__ H, __nv_bfloat16* __restrict__ bt) {
    __shared__ float sH[64][BN + 1];
    const int k0 = blockIdx.x * 64;
    const int tid = threadIdx.x;
    for (int idx = tid; idx < 64 * BN; idx += 256) {
        int r = idx / BN, n = idx % BN;
        sH[r][n] = H[(size_t)(k0 + r) * BN + n];
    }
    __syncthreads();
    const int w = tid >> 5, p = tid & 31;
    const size_t MATB = (size_t)NN * BN;
    for (int n = w; n < BN; n += 8) {
        unsigned hi, lo;
        split2(sH[2 * p][n], sH[2 * p + 1][n], hi, lo);
        *reinterpret_cast<unsigned*>(bt + (size_t)n * NN + k0 + 2 * p) = hi;
        *reinterpret_cast<unsigned*>(bt + MATB + (size_t)n * NN + k0 + 2 * p) = lo;
    }
}

// ---------------- mma.sync layer GEMM: D = adjmix @ H (3-term bf16 split) ---
// BM=128, BK=32, grid (64, SPLITK), 256 threads, 3-stage cp.async pipeline.
template <int BN>
__global__ __launch_bounds__(256, 1)
void gemm_ws(const __nv_bfloat16* __restrict__ ahi, const __nv_bfloat16* __restrict__ alo,
             const __nv_bfloat16* __restrict__ btg, float* __restrict__ part) {
    extern __shared__ char smem[];
    constexpr int ATILE = 128 * 80;           // bytes, one A plane (hi or lo)
    constexpr int ASTG = 2 * ATILE;           // 20480
    constexpr int BTILE = BN * 80;
    constexpr int BSTG = 2 * BTILE;
    constexpr int STG = ASTG + BSTG;          // per pipeline stage
    constexpr int KCH = NN / SPLITK;          // 2048
    constexpr int NITER = KCH / 32;           // 64
    constexpr size_t MATB = (size_t)NN * BN;  // elements per B plane
    constexpr int MT = (BN == 128) ? 2 : 1;
    constexpr int NT = (BN == 128) ? 8 : 2;

    const int tid = threadIdx.x, wid = tid >> 5, lane = tid & 31;
    const int r0 = blockIdx.x * 128;
    const int kBeg = blockIdx.y * KCH;
    const uint32_t sb = smem_to_u32(smem);
    const int wm = (BN == 128) ? (wid & 3) : wid;
    const int wn = (BN == 128) ? (wid >> 2) : 0;
    const int mBase = wm * (MT * 16);
    const int nBase = wn * (NT * 8);

    float acc[MT][NT][4];
    #pragma unroll
    for (int i = 0; i < MT; i++)
        #pragma unroll
        for (int j = 0; j < NT; j++)
            #pragma unroll
            for (int q = 0; q < 4; q++) acc[i][j][q] = 0.f;

    // one pipeline stage: A (hi+lo planes) + B (hi+lo planes), all cp.async
    auto cpStage = [&](int it, int s) {
        const int kofs = kBeg + it * 32;
        // A: 2 planes x 128 rows x 4 chunks(16B) = 1024 chunks
        #pragma unroll
        for (int j = 0; j < 4; j++) {
            int id = tid + j * 256;
            int buf = id >> 9, rem = id & 511;
            int row = rem >> 2, c4 = rem & 3;
            const __nv_bfloat16* src =
                (buf ? alo : ahi) + (size_t)(r0 + row) * NN + kofs + c4 * 8;
            uint32_t dst = sb + s * STG + buf * ATILE + row * 80 + c4 * 16;
            CP_ASYNC16(dst, src);
        }
        // B: 2 planes x BN rows x 4 chunks
        if (BN == 128) {
            #pragma unroll
            for (int j = 0; j < 4; j++) {
                int id = tid + j * 256;
                int buf = id >> 9, rem = id & 511;
                int n = rem >> 2, c4 = rem & 3;
                const __nv_bfloat16* src = btg + (size_t)buf * MATB + (size_t)n * NN + kofs + c4 * 8;
                uint32_t dst = sb + s * STG + ASTG + buf * BTILE + n * 80 + c4 * 16;
                CP_ASYNC16(dst, src);
            }
        } else {
            if (tid < 128) {
                int buf = tid >> 6, rem = tid & 63;
                int n = rem >> 2, c4 = rem & 3;
                const __nv_bfloat16* src = btg + (size_t)buf * MATB + (size_t)n * NN + kofs + c4 * 8;
                uint32_t dst = sb + s * STG + ASTG + buf * BTILE + n * 80 + c4 * 16;
                CP_ASYNC16(dst, src);
            }
        }
        CP_COMMIT();
    };

    auto domma = [&](int s) {
        const uint32_t as = sb + s * STG;
        const uint32_t bs = as + ASTG;
        #pragma unroll
        for (int kk = 0; kk < 2; kk++) {
            uint32_t ah[MT][4], al[MT][4];
            #pragma unroll
            for (int mi = 0; mi < MT; mi++) {
                uint32_t ra = (mBase + mi * 16 + (lane & 15)) * 80
                            + ((lane >> 4) << 4) + kk * 32;
                ldsm4(as + ra, ah[mi][0], ah[mi][1], ah[mi][2], ah[mi][3]);
                ldsm4(as + ATILE + ra, al[mi][0], al[mi][1], al[mi][2], al[mi][3]);
            }
            uint32_t bh[NT][2], bl[NT][2];
            #pragma unroll
            for (int np = 0; np < NT / 2; np++) {
                uint32_t rb = (nBase + np * 16 + ((lane >> 4) << 3) + (lane & 7)) * 80
                            + (((lane >> 3) & 1) << 4) + kk * 32;
                ldsm4(bs + rb, bh[2 * np][0], bh[2 * np][1], bh[2 * np + 1][0], bh[2 * np + 1][1]);
                ldsm4(bs + BTILE + rb, bl[2 * np][0], bl[2 * np][1], bl[2 * np + 1][0], bl[2 * np + 1][1]);
            }
            #pragma unroll
            for (int mi = 0; mi < MT; mi++)
                #pragma unroll
                for (int ni = 0; ni < NT; ni++) {
                    mma16816(acc[mi][ni], ah[mi], bh[ni]);   // hi * hi
                    mma16816(acc[mi][ni], ah[mi], bl[ni]);   // hi * lo
                    mma16816(acc[mi][ni], al[mi], bh[ni]);   // lo * hi
                }
        }
    };

    // 3-stage pipeline
    cpStage(0, 0);
    cpStage(1, 1);
    for (int it = 0; it < NITER; ++it) {
        const int s = it % 3;
        if (it == NITER - 1) { CP_WAIT0(); } else { CP_WAIT1(); }
        __syncthreads();
        if (it + 2 < NITER) cpStage(it + 2, (it + 2) % 3);
        domma(s);
    }

    float* op0 = part + (size_t)blockIdx.y * ((size_t)NN * BN);
    #pragma unroll
    for (int mi = 0; mi < MT; mi++)
        #pragma unroll
        for (int ni = 0; ni < NT; ni++) {
            int row = r0 + mBase + mi * 16 + (lane >> 2);
            int col = nBase + ni * 8 + (lane & 3) * 2;
            *reinterpret_cast<float2*>(op0 + (size_t)row * BN + col) =
                make_float2(acc[mi][ni][0], acc[mi][ni][1]);
            *reinterpret_cast<float2*>(op0 + (size_t)(row + 8) * BN + col) =
                make_float2(acc[mi][ni][2], acc[mi][ni][3]);
        }
}

// ---------------- FFMA SGEMM for the small dense GEMMs (x@W1, h@Wm) --------
__global__ __launch_bounds__(128)
void gemm128_k(const float* __restrict__ A0, const float* __restrict__ Bm,
               float* __restrict__ part, int K, int kPerSplit) {
    __shared__ float As[16][64];
    __shared__ float Bs[16][128];
    const int r0 = blockIdx.x * 64;
    const int kBeg = blockIdx.y * kPerSplit;
    const int tid = threadIdx.x;
    float acc[8][8];
    #pragma unroll
    for (int i = 0; i < 8; i++)
        #pragma unroll
        for (int j = 0; j < 8; j++) acc[i][j] = 0.f;
    const int tm = (tid >> 4) << 3;
    const int tn = (tid & 15) << 3;
    const int qa = tid << 1;
    const int am = qa >> 2;
    const int ak = (qa & 3) << 2;
    for (int kt = kBeg; kt < kBeg + kPerSplit; kt += 16) {
        {
            const float* rp0 = A0 + (size_t)(r0 + am) * (size_t)K + kt + ak;
            float4 v0a = *reinterpret_cast<const float4*>(rp0);
            float4 v0b = *reinterpret_cast<const float4*>(rp0 + 4);
            As[ak + 0][am] = v0a.x; As[ak + 1][am] = v0a.y;
            As[ak + 2][am] = v0a.z; As[ak + 3][am] = v0a.w;
            As[ak + 4][am] = v0b.x; As[ak + 5][am] = v0b.y;
            As[ak + 6][am] = v0b.z; As[ak + 7][am] = v0b.w;
        }
        #pragma unroll
        for (int i = 0; i < 4; i++) {
            int q = tid + (i << 7);
            int k = q >> 5;
            int n4 = (q & 31) << 2;
            *reinterpret_cast<float4*>(&Bs[k][n4]) =
                *reinterpret_cast<const float4*>(Bm + (size_t)(kt + k) * NHID + n4);
        }
        __syncthreads();
        #pragma unroll
        for (int kk = 0; kk < 16; kk++) {
            float4 a0v = *reinterpret_cast<const float4*>(&As[kk][tm]);
            float4 a1v = *reinterpret_cast<const float4*>(&As[kk][tm + 4]);
            float4 b0v = *reinterpret_cast<const float4*>(&Bs[kk][tn]);
            float4 b1v = *reinterpret_cast<const float4*>(&Bs[kk][tn + 4]);
            float rav[8] = {a0v.x, a0v.y, a0v.z, a0v.w, a1v.x, a1v.y, a1v.z, a1v.w};
            float rbv[8] = {b0v.x, b0v.y, b0v.z, b0v.w, b1v.x, b1v.y, b1v.z, b1v.w};
            #pragma unroll
            for (int i = 0; i < 8; i++)
                #pragma unroll
                for (int j = 0; j < 8; j++)
                    acc[i][j] = fmaf(rav[i], rbv[j], acc[i][j]);
        }
        __syncthreads();
    }
    float* p = part + (size_t)blockIdx.y * ((size_t)NN * NHID);
    #pragma unroll
    for (int i = 0; i < 8; i++) {
        float* o = p + (size_t)(r0 + tm + i) * NHID + tn;
        #pragma unroll
        for (int j = 0; j < 8; j++) o[j] = acc[i][j];
    }
}

// ---------------- split-K reduce + bias + relu (width 128) -----------------
__global__ void reduce_ep(const float* __restrict__ part, const float* __restrict__ bias,
                          float* __restrict__ outp, int doRelu) {
    int idx = blockIdx.x * blockDim.x + threadIdx.x;
    const int stride = NN * NHID;
    float s = part[idx] + part[idx + stride] + part[idx + 2 * stride] + part[idx + 3 * stride];
    if (bias) s += bias[idx & (NHID - 1)];
    if (doRelu) s = fmaxf(s, 0.f);
    outp[idx] = s;
}

// ---------------- h2 @ W2 ----------------
__global__ void hw2_kernel(const float* __restrict__ h, const float* __restrict__ W2,
                           float* __restrict__ outp) {
    __shared__ float sW[NHID * NCLASS];
    __shared__ float sH[16][NHID];
    int tid = threadIdx.x;
    for (int i = tid; i < NHID * NCLASS; i += 256) sW[i] = W2[i];
    int r0 = blockIdx.x * 16;
    for (int i = tid; i < 16 * NHID; i += 256) sH[i >> 7][i & 127] = h[(size_t)r0 * NHID + i];
    __syncthreads();
    int r = tid >> 4, n = tid & 15;
    float acc = 0.f;
    #pragma unroll 8
    for (int k = 0; k < NHID; k++) acc = fmaf(sH[r][k], sW[k * NCLASS + n], acc);
    outp[(size_t)(r0 + r) * NCLASS + n] = acc;
}

// ---------------- final: reduce splits + bias + row softmax ----------------
__global__ void final16_kernel(const float* __restrict__ part, const float* __restrict__ b2,
                               float* __restrict__ outp) {
    int gid = blockIdx.x * 256 + threadIdx.x;
    int n = gid & 15;
    float z = b2[n];
    const int stride = NN * NCLASS;
    #pragma unroll
    for (int s = 0; s < SPLITK; s++) z += part[s * stride + gid];
    float m = z;
    #pragma unroll
    for (int o = 8; o > 0; o >>= 1) m = fmaxf(m, __shfl_xor_sync(0xffffffffu, m, o));
    float e = expf(z - m);
    float ss = e;
    #pragma unroll
    for (int o = 8; o > 0; o >>= 1) ss += __shfl_xor_sync(0xffffffffu, ss, o);
    outp[gid] = e / ss;
}

// ---------------- launch ---------------------------------------------------
extern "C" void kernel_launch(void* const* d_in, const int* in_sizes, int n_in,
                              void* d_out, int out_size) {
    const float* adj0 = (const float*)d_in[0];
    const float* adj1 = (const float*)d_in[1];
    const float* x    = (const float*)d_in[2];
    const float* aw   = (const float*)d_in[3];
    const float* ab   = (const float*)d_in[4];
    const float* W1   = (const float*)d_in[5];
    const float* b1   = (const float*)d_in[6];
    const float* Wm   = (const float*)d_in[7];
    const float* bm   = (const float*)d_in[8];
    const float* W2   = (const float*)d_in[9];
    const float* b2   = (const float*)d_in[10];
    float* out = (float*)d_out;

    float *pB, *ph, *pB16, *ppart, *ppart16;
    __nv_bfloat16 *pbt, *pahi, *palo;
    cudaGetSymbolAddress((void**)&pB, g_B);
    cudaGetSymbolAddress((void**)&ph, g_h);
    cudaGetSymbolAddress((void**)&pB16, g_B16);
    cudaGetSymbolAddress((void**)&ppart, g_part);
    cudaGetSymbolAddress((void**)&ppart16, g_part16);
    cudaGetSymbolAddress((void**)&pbt, g_bt);
    cudaGetSymbolAddress((void**)&pahi, g_ahi);
    cudaGetSymbolAddress((void**)&palo, g_alo);

    const int SMEM128 = 3 * (2 * 128 * 80 + 2 * 128 * 80);  // 122880
    const int SMEM16  = 3 * (2 * 128 * 80 + 2 * 16 * 80);   //  69120
    cudaFuncSetAttribute(gemm_ws<128>, cudaFuncAttributeMaxDynamicSharedMemorySize, SMEM128);
    cudaFuncSetAttribute(gemm_ws<16>,  cudaFuncAttributeMaxDynamicSharedMemorySize, SMEM16);

    // attention column weights, then premix adj into bf16 hi/lo planes
    attn_kernel<<<NN, 256>>>(adj0, adj1, aw, ab);
    premix_kernel<<<NN, 256>>>(adj0, adj1, pahi, palo);

    // H0 = x @ W1
    gemm128_k<<<dim3(NN / 64, SPLITK), 128>>>(x, W1, ppart, NFEAT, NFEAT / SPLITK);
    reduce_ep<<<NN * NHID / 256, 256>>>(ppart, nullptr, pB, 0);

    // h1 = relu(adjmix @ H0 + b1)
    prep_bt<128><<<128, 256>>>(pB, pbt);
    gemm_ws<128><<<dim3(NN / 128, SPLITK), 256, SMEM128>>>(pahi, palo, pbt, ppart);
    reduce_ep<<<NN * NHID / 256, 256>>>(ppart, b1, ph, 1);

    // H1 = h1 @ Wm
    gemm128_k<<<dim3(NN / 64, SPLITK), 128>>>(ph, Wm, ppart, NHID, NHID / SPLITK);
    reduce_ep<<<NN * NHID / 256, 256>>>(ppart, nullptr, pB, 0);

    // h2 = relu(adjmix @ H1 + bm)
    prep_bt<128><<<128, 256>>>(pB, pbt);
    gemm_ws<128><<<dim3(NN / 128, SPLITK), 256, SMEM128>>>(pahi, palo, pbt, ppart);
    reduce_ep<<<NN * NHID / 256, 256>>>(ppart, bm, ph, 1);

    // H2 = h2 @ W2
    hw2_kernel<<<NN / 16, 256>>>(ph, W2, pB16);

    // z = adjmix @ H2 + b2 ; softmax rows
    prep_bt<16><<<128, 256>>>(pB16, pbt);
    gemm_ws<16><<<dim3(NN / 128, SPLITK), 256, SMEM16>>>(pahi, palo, pbt, ppart16);
    final16_kernel<<<NN * NCLASS / 256, 256>>>(ppart16, b2, out);
}